// round 10
// baseline (speedup 1.0000x reference)
#include <cuda_runtime.h>
#include <math.h>

#define NV 100000
#define NU 40000
#define NI 60000
#define HIDDIM 256
#define ME 500000
#define BSZ 4096
#define NLAYERS 5
#define RIT 7

#define RWARPS 4           // warps per route block
#define CAPR 4             // register slots per lane (2 streams -> 8 edges in regs)
#define CAPS 14            // smem-cached edges (edges 8..21)
#define MAXDEG 64          // hard cap on degree (Poisson(12.5))
#define KSTRIDE 36         // floats per capsule in smem (32 + 4 pad)
#define ESTRIDE (8 * KSTRIDE)   // 288 floats per cached edge row
// 4*14*288*4 + 4*64*4 = 65536 B per CTA -> 3 CTAs/SM
#define ROUTE_SMEM ((RWARPS * CAPS * ESTRIDE) * 4 + RWARPS * MAXDEG * 4)

typedef unsigned long long u64;

// ---------------- packed f32x2 helpers ----------------
__device__ __forceinline__ u64 f2fma(u64 a, u64 b, u64 c) {
    u64 d; asm("fma.rn.f32x2 %0,%1,%2,%3;" : "=l"(d) : "l"(a), "l"(b), "l"(c)); return d;
}
__device__ __forceinline__ u64 f2mul(u64 a, u64 b) {
    u64 d; asm("mul.rn.f32x2 %0,%1,%2;" : "=l"(d) : "l"(a), "l"(b)); return d;
}
__device__ __forceinline__ u64 f2add(u64 a, u64 b) {
    u64 d; asm("add.rn.f32x2 %0,%1,%2;" : "=l"(d) : "l"(a), "l"(b)); return d;
}
__device__ __forceinline__ u64 fpack(float x, float y) {
    u64 d; asm("mov.b64 %0,{%1,%2};" : "=l"(d) : "f"(x), "f"(y)); return d;
}
__device__ __forceinline__ float2 funpack(u64 a) {
    float2 r; asm("mov.b64 {%0,%1},%2;" : "=f"(r.x), "=f"(r.y) : "l"(a)); return r;
}

// ---------------- scratch ----------------
__device__ float g_Z[(size_t)NV * HIDDIM];   // features; item rows constant after init
__device__ int   g_rowptr[NU + 1];
__device__ int   g_cursor[NU];
__device__ int   g_trgs[ME];

// ---------------- 1) SGEMM: g_Z = X @ W + b ----------------
__global__ void gemm_bias_kernel(const float* __restrict__ X,
                                 const float* __restrict__ W,
                                 const float* __restrict__ bias) {
    __shared__ float As[16][65];
    __shared__ __align__(16) float Bs[16][64];
    int tid = threadIdx.x;
    int tx = tid & 15, ty = tid >> 4;
    int row0 = blockIdx.x * 64;
    int col0 = blockIdx.y * 64;
    u64 acc2[4][2];
#pragma unroll
    for (int i = 0; i < 4; i++) { acc2[i][0] = 0ull; acc2[i][1] = 0ull; }

    for (int k0 = 0; k0 < 256; k0 += 16) {
        int ar = tid >> 2;
        int ac = (tid & 3) << 2;
        int arow = row0 + ar;
        if (arow >= NV) arow = NV - 1;
        float4 av = *(const float4*)(X + (size_t)arow * 256 + k0 + ac);
        As[ac + 0][ar] = av.x; As[ac + 1][ar] = av.y;
        As[ac + 2][ar] = av.z; As[ac + 3][ar] = av.w;
        int br = tid >> 4;
        int bc = (tid & 15) << 2;
        float4 bv = *(const float4*)(W + (size_t)(k0 + br) * 256 + col0 + bc);
        *(float4*)&Bs[br][bc] = bv;
        __syncthreads();
#pragma unroll
        for (int kk = 0; kk < 16; kk++) {
            ulonglong2 bq = *(ulonglong2*)&Bs[kk][tx << 2];
            float a0 = As[kk][(ty << 2) + 0];
            float a1 = As[kk][(ty << 2) + 1];
            float a2 = As[kk][(ty << 2) + 2];
            float a3 = As[kk][(ty << 2) + 3];
            u64 ap0 = fpack(a0, a0), ap1 = fpack(a1, a1);
            u64 ap2 = fpack(a2, a2), ap3 = fpack(a3, a3);
            acc2[0][0] = f2fma(ap0, bq.x, acc2[0][0]); acc2[0][1] = f2fma(ap0, bq.y, acc2[0][1]);
            acc2[1][0] = f2fma(ap1, bq.x, acc2[1][0]); acc2[1][1] = f2fma(ap1, bq.y, acc2[1][1]);
            acc2[2][0] = f2fma(ap2, bq.x, acc2[2][0]); acc2[2][1] = f2fma(ap2, bq.y, acc2[2][1]);
            acc2[3][0] = f2fma(ap3, bq.x, acc2[3][0]); acc2[3][1] = f2fma(ap3, bq.y, acc2[3][1]);
        }
        __syncthreads();
    }
#pragma unroll
    for (int i = 0; i < 4; i++) {
        int row = row0 + (ty << 2) + i;
        if (row < NV) {
            int col = col0 + (tx << 2);
            float4 bv = *(const float4*)(bias + col);
            float2 lo = funpack(acc2[i][0]);
            float2 hi = funpack(acc2[i][1]);
            float4 o;
            o.x = lo.x + bv.x; o.y = lo.y + bv.y;
            o.z = hi.x + bv.z; o.w = hi.y + bv.w;
            *(float4*)(g_Z + (size_t)row * 256 + col) = o;
        }
    }
}

// ---------------- 2) init: Z = l2norm(relu(Z)) per (node, k) ----------------
__global__ void init_norm_kernel() {
    int warp = (blockIdx.x * blockDim.x + threadIdx.x) >> 5;
    int lane = threadIdx.x & 31;
    if (warp >= NV) return;
    float* row = g_Z + (size_t)warp * 256 + lane * 8;
    float4 a = *(float4*)row;
    float4 b = *(float4*)(row + 4);
    float v[8] = {a.x, a.y, a.z, a.w, b.x, b.y, b.z, b.w};
    float ss = 0.f;
#pragma unroll
    for (int j = 0; j < 8; j++) { v[j] = fmaxf(v[j], 0.f); ss = fmaf(v[j], v[j], ss); }
    ss += __shfl_xor_sync(0xffffffffu, ss, 1);
    ss += __shfl_xor_sync(0xffffffffu, ss, 2);
    float inv = 1.f / fmaxf(sqrtf(ss), 1e-12f);
#pragma unroll
    for (int j = 0; j < 8; j++) v[j] *= inv;
    *(float4*)row = make_float4(v[0], v[1], v[2], v[3]);
    *(float4*)(row + 4) = make_float4(v[4], v[5], v[6], v[7]);
}

// ---------------- 3) CSR build (deterministic) ----------------
__global__ void zero_hist_kernel() {
    int i = blockIdx.x * blockDim.x + threadIdx.x;
    if (i <= NU) g_rowptr[i] = 0;
}
__global__ void hist_kernel(const int* __restrict__ edges) {
    int m = blockIdx.x * blockDim.x + threadIdx.x;
    if (m < ME) atomicAdd(&g_rowptr[edges[m] + 1], 1);
}
__global__ void scan_kernel() {
    __shared__ int s[1024];
    int t = threadIdx.x;
    const int per = (NU + 1023) / 1024;
    int start = t * per;
    int end = start + per; if (end > NU) end = NU;
    int sum = 0;
    for (int i = start; i < end; i++) sum += g_rowptr[1 + i];
    s[t] = sum;
    __syncthreads();
    for (int off = 1; off < 1024; off <<= 1) {
        int v = (t >= off) ? s[t - off] : 0;
        __syncthreads();
        s[t] += v;
        __syncthreads();
    }
    int base = (t == 0) ? 0 : s[t - 1];
    int run = base;
    for (int i = start; i < end; i++) {
        run += g_rowptr[1 + i];
        g_rowptr[1 + i] = run;
    }
    if (t == 0) g_rowptr[0] = 0;
}
__global__ void cursor_kernel() {
    int i = blockIdx.x * blockDim.x + threadIdx.x;
    if (i < NU) g_cursor[i] = g_rowptr[i];
}
__global__ void scatter_kernel(const int* __restrict__ edges) {
    int m = blockIdx.x * blockDim.x + threadIdx.x;
    if (m >= ME) return;
    int src = edges[m];
    int trg = edges[ME + m];
    int p = atomicAdd(&g_cursor[src], 1);
    g_trgs[p] = trg;
}
__global__ void bucketsort_kernel() {
    int u = blockIdx.x * blockDim.x + threadIdx.x;
    if (u >= NU) return;
    int e0 = g_rowptr[u], e1 = g_rowptr[u + 1];
    for (int i = e0 + 1; i < e1; i++) {
        int key = g_trgs[i];
        int j = i - 1;
        while (j >= e0 && g_trgs[j] > key) { g_trgs[j + 1] = g_trgs[j]; j--; }
        g_trgs[j + 1] = key;
    }
}

// ---- dot of one cached edge against c2 (half-capsule, packed) ----
__device__ __forceinline__ float half_dot(const u64 zt2[8], const u64 c2[8]) {
    u64 da = f2mul(zt2[0], c2[0]);
    u64 db = f2mul(zt2[1], c2[1]);
#pragma unroll
    for (int j = 2; j < 8; j += 2) {
        da = f2fma(zt2[j], c2[j], da);
        db = f2fma(zt2[j + 1], c2[j + 1], db);
    }
    float2 dd = funpack(f2add(da, db));
    return dd.x + dd.y;
}

// ---- full serial pass (LDG tail only; rare) ----
__device__ __forceinline__ void route_pass(const u64 zt2[8], const u64 c2[8],
                                           u64 agg2[8], bool active) {
    float dot = half_dot(zt2, c2);
    dot += __shfl_xor_sync(0xffffffffu, dot, 1);
    float ex = __expf(dot);
    float sm = ex;
    sm += __shfl_xor_sync(0xffffffffu, sm, 2);
    sm += __shfl_xor_sync(0xffffffffu, sm, 4);
    sm += __shfl_xor_sync(0xffffffffu, sm, 8);
    float pw = active ? __fdividef(ex, sm) : 0.f;
    u64 pw2 = fpack(pw, pw);
#pragma unroll
    for (int j = 0; j < 8; j++) agg2[j] = f2fma(pw2, zt2[j], agg2[j]);
}

// ---------------- 4) fused routing: single batched softmax per iteration --------
// Lane = eslot*16 + k*2 + h; lane owns half-capsule (16 floats), 2 edges/pass.
// Edges 0..7 in REGISTERS, 8..21 in smem, 22+ LDG. Batch 0 covers the reg chunk
// plus the first 4 smem passes (edges <=15, 87% of warps) in ONE phase-split
// softmax chain; deg>=17 pays a second predicated mini-batch.
__global__ void __launch_bounds__(RWARPS * 32, 3) route_mega_kernel() {
    extern __shared__ float smem[];
    int w = threadIdx.x >> 5;
    int lane = threadIdx.x & 31;
    int u = blockIdx.x * RWARPS + w;          // 10000 * 4 == 40000

    float* zt_s = smem + w * (CAPS * ESTRIDE);
    int* trg = (int*)(smem + RWARPS * CAPS * ESTRIDE) + w * MAXDEG;

    int e0 = g_rowptr[u];
    int deg = g_rowptr[u + 1] - e0;
    if (deg > MAXDEG) deg = MAXDEG;

    for (int i = lane; i < deg; i += 32) trg[i] = g_trgs[e0 + i];
    __syncwarp();

    const int k = (lane >> 1) & 7;
    const int h = lane & 1;
    const int eslot = lane >> 4;

    // ---- register cache: slot s holds edge 2s+eslot (zero-padded) ----
    u64 zc[CAPR][8];
#pragma unroll
    for (int s = 0; s < CAPR; s++) {
        int e = 2 * s + eslot;
        if (e < deg) {
            const ulonglong2* gz =
                (const ulonglong2*)(g_Z + (size_t)trg[e] * 256 + k * 32 + h * 16);
#pragma unroll
            for (int i = 0; i < 4; i++) {
                ulonglong2 v = __ldg(gz + i);
                zc[s][2 * i] = v.x; zc[s][2 * i + 1] = v.y;
            }
        } else {
#pragma unroll
            for (int j = 0; j < 8; j++) zc[s][j] = 0ull;
        }
    }

    // ---- smem cache: edges [2*CAPR, min(deg, 2*CAPR+CAPS)) ----
    int ns = deg - 2 * CAPR;
    if (ns < 0) ns = 0;
    if (ns > CAPS) ns = CAPS;
    for (int e = 0; e < ns; e++) {
        const float4* gz = (const float4*)(g_Z + (size_t)trg[2 * CAPR + e] * 256);
#pragma unroll
        for (int r = 0; r < 2; r++) {
            int f = lane + r * 32;
            float4 v = __ldg(gz + f);
            *(float4*)(zt_s + e * ESTRIDE + (f >> 3) * KSTRIDE + (f & 7) * 4) = v;
        }
    }
    if (ns == 0) {   // keep slot 0 finite: pw=0 * NaN would poison agg
#pragma unroll
        for (int r = 0; r < 2; r++) {
            int f = lane + r * 32;
            *(float4*)(zt_s + (f >> 3) * KSTRIDE + (f & 7) * 4) =
                make_float4(0.f, 0.f, 0.f, 0.f);
        }
    }
    __syncwarp();

    u64 zu2[8], c2[8], agg2[8];
    {
        const ulonglong2* gz = (const ulonglong2*)(g_Z + (size_t)u * 256 + k * 32 + h * 16);
#pragma unroll
        for (int i = 0; i < 4; i++) {
            ulonglong2 v = __ldg(gz + i);
            zu2[2 * i] = v.x; zu2[2 * i + 1] = v.y;
        }
    }
#pragma unroll
    for (int j = 0; j < 8; j++) c2[j] = zu2[j];

    const int npass_s = (ns + 1) >> 1;
    bool actR[CAPR];
#pragma unroll
    for (int s = 0; s < CAPR; s++) actR[s] = (2 * s + eslot) < deg;
    // smem pass activity + slot indices (loop-invariant)
    bool actS[7];
    int eeS[7];
#pragma unroll
    for (int p = 0; p < 7; p++) {
        int e = 2 * p + eslot;
        actS[p] = (p < npass_s) && (e < ns);
        eeS[p] = actS[p] ? e : 0;
    }
    const bool has2 = npass_s > 4;

#pragma unroll 1
    for (int layer = 0; layer < NLAYERS; layer++) {
        if (layer) {
#pragma unroll
            for (int j = 0; j < 8; j++) {
                float2 t = funpack(c2[j]);
                t.x = fmaxf(t.x, 0.f); t.y = fmaxf(t.y, 0.f);
                zu2[j] = fpack(t.x, t.y);
                c2[j] = zu2[j];
            }
        }
#pragma unroll 1
        for (int it = 0; it < RIT; it++) {
#pragma unroll
            for (int j = 0; j < 8; j++) agg2[j] = 0ull;

            // ===== batch 0: 4 reg passes + smem passes 0..3, ONE softmax phase ====
            {
                float dt[8], exv[8], smv[8];
                // smem dots first (LDS latency overlaps reg-dot FMAs)
#pragma unroll
                for (int q = 0; q < 4; q++) {
                    u64 zt2[8];
                    const ulonglong2* sz =
                        (const ulonglong2*)(zt_s + eeS[q] * ESTRIDE + k * KSTRIDE + h * 16);
#pragma unroll
                    for (int i = 0; i < 4; i++) {
                        ulonglong2 v = sz[i];
                        zt2[2 * i] = v.x; zt2[2 * i + 1] = v.y;
                    }
                    float d = half_dot(zt2, c2);
                    dt[4 + q] = actS[q] ? d : 0.f;
                }
#pragma unroll
                for (int s = 0; s < CAPR; s++) dt[s] = half_dot(zc[s], c2);
                // batched softmax: 8 independent shfl/MUFU pipelines
#pragma unroll
                for (int q = 0; q < 8; q++) dt[q] += __shfl_xor_sync(0xffffffffu, dt[q], 1);
#pragma unroll
                for (int q = 0; q < 8; q++) exv[q] = __expf(dt[q]);
#pragma unroll
                for (int q = 0; q < 8; q++) smv[q] = exv[q] + __shfl_xor_sync(0xffffffffu, exv[q], 2);
#pragma unroll
                for (int q = 0; q < 8; q++) smv[q] += __shfl_xor_sync(0xffffffffu, smv[q], 4);
#pragma unroll
                for (int q = 0; q < 8; q++) smv[q] += __shfl_xor_sync(0xffffffffu, smv[q], 8);
                // accumulates: reg slots, then smem reload
#pragma unroll
                for (int s = 0; s < CAPR; s++) {
                    float pw = actR[s] ? __fdividef(exv[s], smv[s]) : 0.f;
                    u64 pw2 = fpack(pw, pw);
#pragma unroll
                    for (int j = 0; j < 8; j++) agg2[j] = f2fma(pw2, zc[s][j], agg2[j]);
                }
#pragma unroll
                for (int q = 0; q < 4; q++) {
                    float pw = actS[q] ? __fdividef(exv[4 + q], smv[4 + q]) : 0.f;
                    u64 pw2 = fpack(pw, pw);
                    const ulonglong2* sz =
                        (const ulonglong2*)(zt_s + eeS[q] * ESTRIDE + k * KSTRIDE + h * 16);
#pragma unroll
                    for (int i = 0; i < 4; i++) {
                        ulonglong2 v = sz[i];
                        agg2[2 * i]     = f2fma(pw2, v.x, agg2[2 * i]);
                        agg2[2 * i + 1] = f2fma(pw2, v.y, agg2[2 * i + 1]);
                    }
                }
            }

            // ===== batch 1 (deg >= 17 only, ~13%): smem passes 4..6 =====
            if (has2) {
                float dt[3], exv[3], smv[3];
#pragma unroll
                for (int q = 0; q < 3; q++) {
                    u64 zt2[8];
                    const ulonglong2* sz =
                        (const ulonglong2*)(zt_s + eeS[4 + q] * ESTRIDE + k * KSTRIDE + h * 16);
#pragma unroll
                    for (int i = 0; i < 4; i++) {
                        ulonglong2 v = sz[i];
                        zt2[2 * i] = v.x; zt2[2 * i + 1] = v.y;
                    }
                    float d = half_dot(zt2, c2);
                    dt[q] = actS[4 + q] ? d : 0.f;
                }
#pragma unroll
                for (int q = 0; q < 3; q++) dt[q] += __shfl_xor_sync(0xffffffffu, dt[q], 1);
#pragma unroll
                for (int q = 0; q < 3; q++) exv[q] = __expf(dt[q]);
#pragma unroll
                for (int q = 0; q < 3; q++) smv[q] = exv[q] + __shfl_xor_sync(0xffffffffu, exv[q], 2);
#pragma unroll
                for (int q = 0; q < 3; q++) smv[q] += __shfl_xor_sync(0xffffffffu, smv[q], 4);
#pragma unroll
                for (int q = 0; q < 3; q++) smv[q] += __shfl_xor_sync(0xffffffffu, smv[q], 8);
#pragma unroll
                for (int q = 0; q < 3; q++) {
                    float pw = actS[4 + q] ? __fdividef(exv[q], smv[q]) : 0.f;
                    u64 pw2 = fpack(pw, pw);
                    const ulonglong2* sz =
                        (const ulonglong2*)(zt_s + eeS[4 + q] * ESTRIDE + k * KSTRIDE + h * 16);
#pragma unroll
                    for (int i = 0; i < 4; i++) {
                        ulonglong2 v = sz[i];
                        agg2[2 * i]     = f2fma(pw2, v.x, agg2[2 * i]);
                        agg2[2 * i + 1] = f2fma(pw2, v.y, agg2[2 * i + 1]);
                    }
                }
            }

            // ===== LDG tail (deg > 22; ~0.4% of warps) =====
#pragma unroll 1
            for (int e = 2 * CAPR + CAPS; e < deg; e += 2) {
                int eidx = e + eslot;
                bool active = eidx < deg;
                int et = active ? eidx : (deg - 1);
                u64 zt2[8];
                const ulonglong2* gz =
                    (const ulonglong2*)(g_Z + (size_t)trg[et] * 256 + k * 32 + h * 16);
#pragma unroll
                for (int i = 0; i < 4; i++) {
                    ulonglong2 v = __ldg(gz + i);
                    zt2[2 * i] = v.x; zt2[2 * i + 1] = v.y;
                }
                route_pass(zt2, c2, agg2, active);
            }

            // combine edge streams (lane bit 4), add zu, l2-normalize
            float nn[16];
            float ss = 0.f;
#pragma unroll
            for (int j = 0; j < 8; j++) {
                float2 t = funpack(agg2[j]);
                t.x += __shfl_xor_sync(0xffffffffu, t.x, 16);
                t.y += __shfl_xor_sync(0xffffffffu, t.y, 16);
                float2 z = funpack(zu2[j]);
                t.x += z.x; t.y += z.y;
                ss = fmaf(t.x, t.x, fmaf(t.y, t.y, ss));
                nn[2 * j] = t.x; nn[2 * j + 1] = t.y;
            }
            ss += __shfl_xor_sync(0xffffffffu, ss, 1);
            float inv = rsqrtf(fmaxf(ss, 1e-24f));
            u64 invp = fpack(inv, inv);
#pragma unroll
            for (int j = 0; j < 8; j++)
                c2[j] = f2mul(fpack(nn[2 * j], nn[2 * j + 1]), invp);
        }
    }

    // final user embedding: Z_u = relu(c). eslot 0 lanes cover the full row.
    if (eslot == 0) {
        ulonglong2* gz = (ulonglong2*)(g_Z + (size_t)u * 256 + k * 32 + h * 16);
#pragma unroll
        for (int i = 0; i < 4; i++) {
            float2 a = funpack(c2[2 * i]);
            float2 b = funpack(c2[2 * i + 1]);
            ulonglong2 o;
            o.x = fpack(fmaxf(a.x, 0.f), fmaxf(a.y, 0.f));
            o.y = fpack(fmaxf(b.x, 0.f), fmaxf(b.y, 0.f));
            gz[i] = o;
        }
    }
}

// ---------------- 5) output gather ----------------
__global__ void gather_kernel(const int* __restrict__ users,
                              const int* __restrict__ pos,
                              const int* __restrict__ neg,
                              float* __restrict__ out) {
    int warp = (blockIdx.x * blockDim.x + threadIdx.x) >> 5;
    int lane = threadIdx.x & 31;
    if (warp >= 3 * BSZ) return;
    int node;
    if (warp < BSZ) node = users[warp];
    else if (warp < 2 * BSZ) node = NU + pos[warp - BSZ];
    else node = NU + neg[warp - 2 * BSZ];
    const float* zr = g_Z + (size_t)node * 256 + lane * 8;
    float4 a = *(const float4*)zr;
    float4 b = *(const float4*)(zr + 4);
    float* orow = out + (size_t)warp * 256 + lane * 8;
    *(float4*)orow = a;
    *(float4*)(orow + 4) = b;
}

// ---------------- launcher ----------------
extern "C" void kernel_launch(void* const* d_in, const int* in_sizes, int n_in,
                              void* d_out, int out_size) {
    const float* X = (const float*)d_in[0];
    const float* W = (const float*)d_in[1];
    const float* b = (const float*)d_in[2];
    const int* edges = (const int*)d_in[3];
    const int* users = (const int*)d_in[4];
    const int* pos = (const int*)d_in[5];
    const int* neg = (const int*)d_in[6];
    float* out = (float*)d_out;

    cudaFuncSetAttribute(route_mega_kernel,
                         cudaFuncAttributeMaxDynamicSharedMemorySize, ROUTE_SMEM);
    cudaFuncSetAttribute(route_mega_kernel,
                         cudaFuncAttributePreferredSharedMemoryCarveout,
                         cudaSharedmemCarveoutMaxShared);

    dim3 ggrid((NV + 63) / 64, 4);
    gemm_bias_kernel<<<ggrid, 256>>>(X, W, b);
    init_norm_kernel<<<(NV * 32 + 255) / 256, 256>>>();

    zero_hist_kernel<<<(NU + 256) / 256, 256>>>();
    hist_kernel<<<(ME + 255) / 256, 256>>>(edges);
    scan_kernel<<<1, 1024>>>();
    cursor_kernel<<<(NU + 255) / 256, 256>>>();
    scatter_kernel<<<(ME + 255) / 256, 256>>>(edges);
    bucketsort_kernel<<<(NU + 255) / 256, 256>>>();

    route_mega_kernel<<<NU / RWARPS, RWARPS * 32, ROUTE_SMEM>>>();

    gather_kernel<<<(3 * BSZ * 32 + 255) / 256, 256>>>(users, pos, neg, out);
}

// round 13
// speedup vs baseline: 1.4983x; 1.4983x over previous
#include <cuda_runtime.h>
#include <math.h>

#define NV 100000
#define NU 40000
#define NI 60000
#define HIDDIM 256
#define ME 500000
#define BSZ 4096
#define NLAYERS 5
#define RIT 7

#define RWARPS 4           // warps per route block
#define CAPR 2             // register slots per lane (2 streams -> 4 edges in regs)
#define CAPS 12            // smem-cached edges (edges 4..15)
#define MAXDEG 64          // hard cap on degree (Poisson(12.5))
#define KSTRIDE 36         // floats per capsule in smem (32 + 4 pad)
#define ESTRIDE (8 * KSTRIDE)   // 288 floats per cached edge row
// 4*12*288*4 + 4*64*4 = 56320 B per CTA -> 4 CTAs/SM (4*56320=225280 <= 228KB)
#define ROUTE_SMEM ((RWARPS * CAPS * ESTRIDE) * 4 + RWARPS * MAXDEG * 4)

typedef unsigned long long u64;

// ---------------- packed f32x2 helpers ----------------
__device__ __forceinline__ u64 f2fma(u64 a, u64 b, u64 c) {
    u64 d; asm("fma.rn.f32x2 %0,%1,%2,%3;" : "=l"(d) : "l"(a), "l"(b), "l"(c)); return d;
}
__device__ __forceinline__ u64 f2mul(u64 a, u64 b) {
    u64 d; asm("mul.rn.f32x2 %0,%1,%2;" : "=l"(d) : "l"(a), "l"(b)); return d;
}
__device__ __forceinline__ u64 f2add(u64 a, u64 b) {
    u64 d; asm("add.rn.f32x2 %0,%1,%2;" : "=l"(d) : "l"(a), "l"(b)); return d;
}
__device__ __forceinline__ u64 fpack(float x, float y) {
    u64 d; asm("mov.b64 %0,{%1,%2};" : "=l"(d) : "f"(x), "f"(y)); return d;
}
__device__ __forceinline__ float2 funpack(u64 a) {
    float2 r; asm("mov.b64 {%0,%1},%2;" : "=f"(r.x), "=f"(r.y) : "l"(a)); return r;
}

// ---------------- scratch ----------------
__device__ float g_Z[(size_t)NV * HIDDIM];   // features; item rows constant after init
__device__ int   g_rowptr[NU + 1];
__device__ int   g_cursor[NU];
__device__ int   g_trgs[ME];

// ---------------- 1) SGEMM: g_Z = X @ W + b ----------------
__global__ void gemm_bias_kernel(const float* __restrict__ X,
                                 const float* __restrict__ W,
                                 const float* __restrict__ bias) {
    __shared__ float As[16][65];
    __shared__ __align__(16) float Bs[16][64];
    int tid = threadIdx.x;
    int tx = tid & 15, ty = tid >> 4;
    int row0 = blockIdx.x * 64;
    int col0 = blockIdx.y * 64;
    u64 acc2[4][2];
#pragma unroll
    for (int i = 0; i < 4; i++) { acc2[i][0] = 0ull; acc2[i][1] = 0ull; }

    for (int k0 = 0; k0 < 256; k0 += 16) {
        int ar = tid >> 2;
        int ac = (tid & 3) << 2;
        int arow = row0 + ar;
        if (arow >= NV) arow = NV - 1;
        float4 av = *(const float4*)(X + (size_t)arow * 256 + k0 + ac);
        As[ac + 0][ar] = av.x; As[ac + 1][ar] = av.y;
        As[ac + 2][ar] = av.z; As[ac + 3][ar] = av.w;
        int br = tid >> 4;
        int bc = (tid & 15) << 2;
        float4 bv = *(const float4*)(W + (size_t)(k0 + br) * 256 + col0 + bc);
        *(float4*)&Bs[br][bc] = bv;
        __syncthreads();
#pragma unroll
        for (int kk = 0; kk < 16; kk++) {
            ulonglong2 bq = *(ulonglong2*)&Bs[kk][tx << 2];
            float a0 = As[kk][(ty << 2) + 0];
            float a1 = As[kk][(ty << 2) + 1];
            float a2 = As[kk][(ty << 2) + 2];
            float a3 = As[kk][(ty << 2) + 3];
            u64 ap0 = fpack(a0, a0), ap1 = fpack(a1, a1);
            u64 ap2 = fpack(a2, a2), ap3 = fpack(a3, a3);
            acc2[0][0] = f2fma(ap0, bq.x, acc2[0][0]); acc2[0][1] = f2fma(ap0, bq.y, acc2[0][1]);
            acc2[1][0] = f2fma(ap1, bq.x, acc2[1][0]); acc2[1][1] = f2fma(ap1, bq.y, acc2[1][1]);
            acc2[2][0] = f2fma(ap2, bq.x, acc2[2][0]); acc2[2][1] = f2fma(ap2, bq.y, acc2[2][1]);
            acc2[3][0] = f2fma(ap3, bq.x, acc2[3][0]); acc2[3][1] = f2fma(ap3, bq.y, acc2[3][1]);
        }
        __syncthreads();
    }
#pragma unroll
    for (int i = 0; i < 4; i++) {
        int row = row0 + (ty << 2) + i;
        if (row < NV) {
            int col = col0 + (tx << 2);
            float4 bv = *(const float4*)(bias + col);
            float2 lo = funpack(acc2[i][0]);
            float2 hi = funpack(acc2[i][1]);
            float4 o;
            o.x = lo.x + bv.x; o.y = lo.y + bv.y;
            o.z = hi.x + bv.z; o.w = hi.y + bv.w;
            *(float4*)(g_Z + (size_t)row * 256 + col) = o;
        }
    }
}

// ---------------- 2) init: Z = l2norm(relu(Z)) per (node, k) ----------------
__global__ void init_norm_kernel() {
    int warp = (blockIdx.x * blockDim.x + threadIdx.x) >> 5;
    int lane = threadIdx.x & 31;
    if (warp >= NV) return;
    float* row = g_Z + (size_t)warp * 256 + lane * 8;
    float4 a = *(float4*)row;
    float4 b = *(float4*)(row + 4);
    float v[8] = {a.x, a.y, a.z, a.w, b.x, b.y, b.z, b.w};
    float ss = 0.f;
#pragma unroll
    for (int j = 0; j < 8; j++) { v[j] = fmaxf(v[j], 0.f); ss = fmaf(v[j], v[j], ss); }
    ss += __shfl_xor_sync(0xffffffffu, ss, 1);
    ss += __shfl_xor_sync(0xffffffffu, ss, 2);
    float inv = 1.f / fmaxf(sqrtf(ss), 1e-12f);
#pragma unroll
    for (int j = 0; j < 8; j++) v[j] *= inv;
    *(float4*)row = make_float4(v[0], v[1], v[2], v[3]);
    *(float4*)(row + 4) = make_float4(v[4], v[5], v[6], v[7]);
}

// ---------------- 3) CSR build (deterministic) ----------------
__global__ void zero_hist_kernel() {
    int i = blockIdx.x * blockDim.x + threadIdx.x;
    if (i <= NU) g_rowptr[i] = 0;
}
__global__ void hist_kernel(const int* __restrict__ edges) {
    int m = blockIdx.x * blockDim.x + threadIdx.x;
    if (m < ME) atomicAdd(&g_rowptr[edges[m] + 1], 1);
}
__global__ void scan_kernel() {
    __shared__ int s[1024];
    int t = threadIdx.x;
    const int per = (NU + 1023) / 1024;
    int start = t * per;
    int end = start + per; if (end > NU) end = NU;
    int sum = 0;
    for (int i = start; i < end; i++) sum += g_rowptr[1 + i];
    s[t] = sum;
    __syncthreads();
    for (int off = 1; off < 1024; off <<= 1) {
        int v = (t >= off) ? s[t - off] : 0;
        __syncthreads();
        s[t] += v;
        __syncthreads();
    }
    int base = (t == 0) ? 0 : s[t - 1];
    int run = base;
    for (int i = start; i < end; i++) {
        run += g_rowptr[1 + i];
        g_rowptr[1 + i] = run;
    }
    if (t == 0) g_rowptr[0] = 0;
}
__global__ void cursor_kernel() {
    int i = blockIdx.x * blockDim.x + threadIdx.x;
    if (i < NU) g_cursor[i] = g_rowptr[i];
}
__global__ void scatter_kernel(const int* __restrict__ edges) {
    int m = blockIdx.x * blockDim.x + threadIdx.x;
    if (m >= ME) return;
    int src = edges[m];
    int trg = edges[ME + m];
    int p = atomicAdd(&g_cursor[src], 1);
    g_trgs[p] = trg;
}
__global__ void bucketsort_kernel() {
    int u = blockIdx.x * blockDim.x + threadIdx.x;
    if (u >= NU) return;
    int e0 = g_rowptr[u], e1 = g_rowptr[u + 1];
    for (int i = e0 + 1; i < e1; i++) {
        int key = g_trgs[i];
        int j = i - 1;
        while (j >= e0 && g_trgs[j] > key) { g_trgs[j + 1] = g_trgs[j]; j--; }
        g_trgs[j + 1] = key;
    }
}

// ---- dot of one cached edge against c2 (half-capsule, packed) ----
__device__ __forceinline__ float half_dot(const u64 zt2[8], const u64 c2[8]) {
    u64 da = f2mul(zt2[0], c2[0]);
    u64 db = f2mul(zt2[1], c2[1]);
#pragma unroll
    for (int j = 2; j < 8; j += 2) {
        da = f2fma(zt2[j], c2[j], da);
        db = f2fma(zt2[j + 1], c2[j + 1], db);
    }
    float2 dd = funpack(f2add(da, db));
    return dd.x + dd.y;
}

// ---- full serial pass (LDG tail only; rare) ----
__device__ __forceinline__ void route_pass(const u64 zt2[8], const u64 c2[8],
                                           u64 agg2[8], bool active) {
    float dot = half_dot(zt2, c2);
    dot += __shfl_xor_sync(0xffffffffu, dot, 1);
    float ex = __expf(dot);
    float sm = ex;
    sm += __shfl_xor_sync(0xffffffffu, sm, 2);
    sm += __shfl_xor_sync(0xffffffffu, sm, 4);
    sm += __shfl_xor_sync(0xffffffffu, sm, 8);
    float pw = active ? __fdividef(ex, sm) : 0.f;
    u64 pw2 = fpack(pw, pw);
#pragma unroll
    for (int j = 0; j < 8; j++) agg2[j] = f2fma(pw2, zt2[j], agg2[j]);
}

// ---------------- 4) fused routing: 4 CTAs/SM, 4-wide lead batch ----------------
// Lane = eslot*16 + k*2 + h; lane owns half-capsule (16 floats), 2 edges/pass.
// Edges 0..3 in REGISTERS, 4..15 in smem, 16+ LDG. Batch A = 2 reg slots +
// smem passes 0..1 in one 4-wide phase-split softmax chain (deg<=8: 1 chain,
// deg<=12: 2 chains). Registers trimmed (CAPR=2, agg2 reused as norm temp) to
// fit 128 regs -> 4 CTAs/SM = 4 warps/SMSP.
__global__ void __launch_bounds__(RWARPS * 32, 4) route_mega_kernel() {
    extern __shared__ float smem[];
    int w = threadIdx.x >> 5;
    int lane = threadIdx.x & 31;
    int u = blockIdx.x * RWARPS + w;          // 10000 * 4 == 40000

    float* zt_s = smem + w * (CAPS * ESTRIDE);
    int* trg = (int*)(smem + RWARPS * CAPS * ESTRIDE) + w * MAXDEG;

    int e0 = g_rowptr[u];
    int deg = g_rowptr[u + 1] - e0;
    if (deg > MAXDEG) deg = MAXDEG;

    for (int i = lane; i < deg; i += 32) trg[i] = g_trgs[e0 + i];
    __syncwarp();

    const int k = (lane >> 1) & 7;
    const int h = lane & 1;
    const int eslot = lane >> 4;

    // ---- register cache: slot s holds edge 2s+eslot (zero-padded) ----
    u64 zc[CAPR][8];
#pragma unroll
    for (int s = 0; s < CAPR; s++) {
        int e = 2 * s + eslot;
        if (e < deg) {
            const ulonglong2* gz =
                (const ulonglong2*)(g_Z + (size_t)trg[e] * 256 + k * 32 + h * 16);
#pragma unroll
            for (int i = 0; i < 4; i++) {
                ulonglong2 v = __ldg(gz + i);
                zc[s][2 * i] = v.x; zc[s][2 * i + 1] = v.y;
            }
        } else {
#pragma unroll
            for (int j = 0; j < 8; j++) zc[s][j] = 0ull;
        }
    }

    // ---- smem cache: edges [2*CAPR, min(deg, 2*CAPR+CAPS)) ----
    int ns = deg - 2 * CAPR;
    if (ns < 0) ns = 0;
    if (ns > CAPS) ns = CAPS;
    for (int e = 0; e < ns; e++) {
        const float4* gz = (const float4*)(g_Z + (size_t)trg[2 * CAPR + e] * 256);
#pragma unroll
        for (int r = 0; r < 2; r++) {
            int f = lane + r * 32;
            float4 v = __ldg(gz + f);
            *(float4*)(zt_s + e * ESTRIDE + (f >> 3) * KSTRIDE + (f & 7) * 4) = v;
        }
    }
    // always keep slots 0..1 finite (batch A reads them unconditionally)
    if (ns < 2) {
#pragma unroll
        for (int e = 0; e < 2; e++) {
            if (ns <= e) {
#pragma unroll
                for (int r = 0; r < 2; r++) {
                    int f = lane + r * 32;
                    *(float4*)(zt_s + e * ESTRIDE + (f >> 3) * KSTRIDE + (f & 7) * 4) =
                        make_float4(0.f, 0.f, 0.f, 0.f);
                }
            }
        }
    }
    __syncwarp();

    u64 zu2[8], c2[8], agg2[8];
    {
        const ulonglong2* gz = (const ulonglong2*)(g_Z + (size_t)u * 256 + k * 32 + h * 16);
#pragma unroll
        for (int i = 0; i < 4; i++) {
            ulonglong2 v = __ldg(gz + i);
            zu2[2 * i] = v.x; zu2[2 * i + 1] = v.y;
        }
    }
#pragma unroll
    for (int j = 0; j < 8; j++) c2[j] = zu2[j];

    const int npass_s = (ns + 1) >> 1;
    bool actR[CAPR];
#pragma unroll
    for (int s = 0; s < CAPR; s++) actR[s] = (2 * s + eslot) < deg;
    bool actA[2];      // smem passes 0..1 (in batch A)
    int eeA[2];
#pragma unroll
    for (int q = 0; q < 2; q++) {
        int e = 2 * q + eslot;
        actA[q] = e < ns;
        eeA[q] = actA[q] ? e : 0;
    }

#pragma unroll 1
    for (int layer = 0; layer < NLAYERS; layer++) {
        if (layer) {
#pragma unroll
            for (int j = 0; j < 8; j++) {
                float2 t = funpack(c2[j]);
                t.x = fmaxf(t.x, 0.f); t.y = fmaxf(t.y, 0.f);
                zu2[j] = fpack(t.x, t.y);
                c2[j] = zu2[j];
            }
        }
#pragma unroll 1
        for (int it = 0; it < RIT; it++) {
#pragma unroll
            for (int j = 0; j < 8; j++) agg2[j] = 0ull;

            // ===== batch A: 2 reg slots + smem passes 0..1, 4-wide phase split ====
            {
                float dt[4], exv[4], smv[4];
#pragma unroll
                for (int q = 0; q < 2; q++) {
                    u64 zt2[8];
                    const ulonglong2* sz =
                        (const ulonglong2*)(zt_s + eeA[q] * ESTRIDE + k * KSTRIDE + h * 16);
#pragma unroll
                    for (int i = 0; i < 4; i++) {
                        ulonglong2 v = sz[i];
                        zt2[2 * i] = v.x; zt2[2 * i + 1] = v.y;
                    }
                    float d = half_dot(zt2, c2);
                    dt[2 + q] = actA[q] ? d : 0.f;
                }
#pragma unroll
                for (int s = 0; s < CAPR; s++) dt[s] = half_dot(zc[s], c2);
#pragma unroll
                for (int q = 0; q < 4; q++) dt[q] += __shfl_xor_sync(0xffffffffu, dt[q], 1);
#pragma unroll
                for (int q = 0; q < 4; q++) exv[q] = __expf(dt[q]);
#pragma unroll
                for (int q = 0; q < 4; q++) smv[q] = exv[q] + __shfl_xor_sync(0xffffffffu, exv[q], 2);
#pragma unroll
                for (int q = 0; q < 4; q++) smv[q] += __shfl_xor_sync(0xffffffffu, smv[q], 4);
#pragma unroll
                for (int q = 0; q < 4; q++) smv[q] += __shfl_xor_sync(0xffffffffu, smv[q], 8);
#pragma unroll
                for (int s = 0; s < CAPR; s++) {
                    float pw = actR[s] ? __fdividef(exv[s], smv[s]) : 0.f;
                    u64 pw2 = fpack(pw, pw);
#pragma unroll
                    for (int j = 0; j < 8; j++) agg2[j] = f2fma(pw2, zc[s][j], agg2[j]);
                }
#pragma unroll
                for (int q = 0; q < 2; q++) {
                    float pw = actA[q] ? __fdividef(exv[2 + q], smv[2 + q]) : 0.f;
                    u64 pw2 = fpack(pw, pw);
                    const ulonglong2* sz =
                        (const ulonglong2*)(zt_s + eeA[q] * ESTRIDE + k * KSTRIDE + h * 16);
#pragma unroll
                    for (int i = 0; i < 4; i++) {
                        ulonglong2 v = sz[i];
                        agg2[2 * i]     = f2fma(pw2, v.x, agg2[2 * i]);
                        agg2[2 * i + 1] = f2fma(pw2, v.y, agg2[2 * i + 1]);
                    }
                }
            }

            // ===== remaining smem chunks: 2 passes each, phase-split =====
#pragma unroll 1
            for (int p0 = 2; p0 < npass_s; p0 += 2) {
                float dt[2], exv[2], smv[2];
                bool act[2];
                int ee[2];
#pragma unroll
                for (int q = 0; q < 2; q++) {
                    int p = p0 + q;
                    int e = 2 * p + eslot;
                    act[q] = (p < npass_s) && (e < ns);
                    ee[q] = act[q] ? e : 0;
                }
#pragma unroll
                for (int q = 0; q < 2; q++) {
                    u64 zt2[8];
                    const ulonglong2* sz =
                        (const ulonglong2*)(zt_s + ee[q] * ESTRIDE + k * KSTRIDE + h * 16);
#pragma unroll
                    for (int i = 0; i < 4; i++) {
                        ulonglong2 v = sz[i];
                        zt2[2 * i] = v.x; zt2[2 * i + 1] = v.y;
                    }
                    dt[q] = half_dot(zt2, c2);
                }
#pragma unroll
                for (int q = 0; q < 2; q++) dt[q] += __shfl_xor_sync(0xffffffffu, dt[q], 1);
#pragma unroll
                for (int q = 0; q < 2; q++) exv[q] = __expf(dt[q]);
#pragma unroll
                for (int q = 0; q < 2; q++) smv[q] = exv[q] + __shfl_xor_sync(0xffffffffu, exv[q], 2);
#pragma unroll
                for (int q = 0; q < 2; q++) smv[q] += __shfl_xor_sync(0xffffffffu, smv[q], 4);
#pragma unroll
                for (int q = 0; q < 2; q++) smv[q] += __shfl_xor_sync(0xffffffffu, smv[q], 8);
#pragma unroll
                for (int q = 0; q < 2; q++) {
                    float pw = act[q] ? __fdividef(exv[q], smv[q]) : 0.f;
                    u64 pw2 = fpack(pw, pw);
                    const ulonglong2* sz =
                        (const ulonglong2*)(zt_s + ee[q] * ESTRIDE + k * KSTRIDE + h * 16);
#pragma unroll
                    for (int i = 0; i < 4; i++) {
                        ulonglong2 v = sz[i];
                        agg2[2 * i]     = f2fma(pw2, v.x, agg2[2 * i]);
                        agg2[2 * i + 1] = f2fma(pw2, v.y, agg2[2 * i + 1]);
                    }
                }
            }

            // ===== LDG tail (deg > 16; ~13% of warps, few passes) =====
#pragma unroll 1
            for (int e = 2 * CAPR + CAPS; e < deg; e += 2) {
                int eidx = e + eslot;
                bool active = eidx < deg;
                int et = active ? eidx : (deg - 1);
                u64 zt2[8];
                const ulonglong2* gz =
                    (const ulonglong2*)(g_Z + (size_t)trg[et] * 256 + k * 32 + h * 16);
#pragma unroll
                for (int i = 0; i < 4; i++) {
                    ulonglong2 v = __ldg(gz + i);
                    zt2[2 * i] = v.x; zt2[2 * i + 1] = v.y;
                }
                route_pass(zt2, c2, agg2, active);
            }

            // combine edge streams (lane bit 16), add zu, l2-normalize.
            // agg2 is reused as the combined-value store (no extra temps).
            float ss = 0.f;
#pragma unroll
            for (int j = 0; j < 8; j++) {
                float2 t = funpack(agg2[j]);
                t.x += __shfl_xor_sync(0xffffffffu, t.x, 16);
                t.y += __shfl_xor_sync(0xffffffffu, t.y, 16);
                float2 z = funpack(zu2[j]);
                t.x += z.x; t.y += z.y;
                ss = fmaf(t.x, t.x, fmaf(t.y, t.y, ss));
                agg2[j] = fpack(t.x, t.y);
            }
            ss += __shfl_xor_sync(0xffffffffu, ss, 1);
            float inv = rsqrtf(fmaxf(ss, 1e-24f));
            u64 invp = fpack(inv, inv);
#pragma unroll
            for (int j = 0; j < 8; j++) c2[j] = f2mul(agg2[j], invp);
        }
    }

    // final user embedding: Z_u = relu(c). eslot 0 lanes cover the full row.
    if (eslot == 0) {
        ulonglong2* gz = (ulonglong2*)(g_Z + (size_t)u * 256 + k * 32 + h * 16);
#pragma unroll
        for (int i = 0; i < 4; i++) {
            float2 a = funpack(c2[2 * i]);
            float2 b = funpack(c2[2 * i + 1]);
            ulonglong2 o;
            o.x = fpack(fmaxf(a.x, 0.f), fmaxf(a.y, 0.f));
            o.y = fpack(fmaxf(b.x, 0.f), fmaxf(b.y, 0.f));
            gz[i] = o;
        }
    }
}

// ---------------- 5) output gather ----------------
__global__ void gather_kernel(const int* __restrict__ users,
                              const int* __restrict__ pos,
                              const int* __restrict__ neg,
                              float* __restrict__ out) {
    int warp = (blockIdx.x * blockDim.x + threadIdx.x) >> 5;
    int lane = threadIdx.x & 31;
    if (warp >= 3 * BSZ) return;
    int node;
    if (warp < BSZ) node = users[warp];
    else if (warp < 2 * BSZ) node = NU + pos[warp - BSZ];
    else node = NU + neg[warp - 2 * BSZ];
    const float* zr = g_Z + (size_t)node * 256 + lane * 8;
    float4 a = *(const float4*)zr;
    float4 b = *(const float4*)(zr + 4);
    float* orow = out + (size_t)warp * 256 + lane * 8;
    *(float4*)orow = a;
    *(float4*)(orow + 4) = b;
}

// ---------------- launcher ----------------
extern "C" void kernel_launch(void* const* d_in, const int* in_sizes, int n_in,
                              void* d_out, int out_size) {
    const float* X = (const float*)d_in[0];
    const float* W = (const float*)d_in[1];
    const float* b = (const float*)d_in[2];
    const int* edges = (const int*)d_in[3];
    const int* users = (const int*)d_in[4];
    const int* pos = (const int*)d_in[5];
    const int* neg = (const int*)d_in[6];
    float* out = (float*)d_out;

    cudaFuncSetAttribute(route_mega_kernel,
                         cudaFuncAttributeMaxDynamicSharedMemorySize, ROUTE_SMEM);
    cudaFuncSetAttribute(route_mega_kernel,
                         cudaFuncAttributePreferredSharedMemoryCarveout,
                         cudaSharedmemCarveoutMaxShared);

    dim3 ggrid((NV + 63) / 64, 4);
    gemm_bias_kernel<<<ggrid, 256>>>(X, W, b);
    init_norm_kernel<<<(NV * 32 + 255) / 256, 256>>>();

    zero_hist_kernel<<<(NU + 256) / 256, 256>>>();
    hist_kernel<<<(ME + 255) / 256, 256>>>(edges);
    scan_kernel<<<1, 1024>>>();
    cursor_kernel<<<(NU + 255) / 256, 256>>>();
    scatter_kernel<<<(ME + 255) / 256, 256>>>(edges);
    bucketsort_kernel<<<(NU + 255) / 256, 256>>>();

    route_mega_kernel<<<NU / RWARPS, RWARPS * 32, ROUTE_SMEM>>>();

    gather_kernel<<<(3 * BSZ * 32 + 255) / 256, 256>>>(users, pos, neg, out);
}